// round 2
// baseline (speedup 1.0000x reference)
#include <cuda_runtime.h>
#include <cstdint>

#define BB 8
#define LL 512
#define CC 6
#define KK 9
#define NTOT (BB*LL)
#define BIGF 1e10f

#define ROWS_PER_BLOCK 8
#define THREADS 256

// Output layout (float32, concatenated in reference return order):
//   [0)            dknn   : NTOT*KK = 36864
//   [36864)        src    : 36864
//   [73728)        dst    : 36864
//   [110592)       valid  : 36864
//   [147456)       glb    : 2 * 8*(2L-1) = 16368
//   [163824)       seq    : 2 * 8*2(L-2) = 16320
// total 180144

__global__ __launch_bounds__(THREADS) void knn_kernel(
    const float* __restrict__ X, const int* __restrict__ AP,
    const int* __restrict__ S, const int* __restrict__ sec,
    float* __restrict__ out)
{
    // stride 19 (odd) -> conflict-free lane access
    __shared__ float sX[LL * 19];         // 38912 B
    __shared__ int   sPad[LL];            // bits0-5 pad, bit6 glb(BOS), bit7 fully-padded
    __shared__ int   sSec[LL];

    const int b     = blockIdx.x / (LL / ROWS_PER_BLOCK);
    const int rg    = blockIdx.x % (LL / ROWS_PER_BLOCK);
    const int gbase = b * LL;

    for (int l = threadIdx.x; l < LL; l += THREADS) {
        const float* xp = X + (size_t)(gbase + l) * (CC * 3);
        int pad = 0;
        #pragma unroll
        for (int c = 0; c < CC; ++c) {
            sX[l * 19 + c * 3 + 0] = xp[c * 3 + 0];
            sX[l * 19 + c * 3 + 1] = xp[c * 3 + 1];
            sX[l * 19 + c * 3 + 2] = xp[c * 3 + 2];
            if (AP[(size_t)(gbase + l) * CC + c] == 0) pad |= (1 << c);
        }
        if (pad == 0x3F) pad |= 0x80;
        if (S[gbase + l] == 0) pad |= 0x40;
        sPad[l] = pad;
        sSec[l] = sec[gbase + l];
    }
    __syncthreads();

    const int warp = threadIdx.x >> 5;
    const int lane = threadIdx.x & 31;
    const int il   = rg * ROWS_PER_BLOCK + warp;   // local row
    const int ig   = gbase + il;                   // global row

    // row-constant data (uniform within warp)
    float xi[CC][3], sqi[CC];
    #pragma unroll
    for (int c = 0; c < CC; ++c) {
        xi[c][0] = sX[il * 19 + c * 3 + 0];
        xi[c][1] = sX[il * 19 + c * 3 + 1];
        xi[c][2] = sX[il * 19 + c * 3 + 2];
        sqi[c] = xi[c][0] * xi[c][0] + xi[c][1] * xi[c][1] + xi[c][2] * xi[c][2];
    }
    const int  padi  = sPad[il];
    const bool glbi  = (padi & 0x40) != 0;
    const bool fulli = (padi & 0x80) != 0;

    unsigned long long best[KK];
    #pragma unroll
    for (int t = 0; t < KK; ++t) best[t] = ~0ull;

    for (int j = lane; j < LL; j += 32) {
        const int padj = sPad[j];
        unsigned long long key;
        if (glbi || (padj & 0x40)) {
            key = (1ull << 41) | (unsigned)j;     // class1: exactly BIGINT, tie by index
        } else {
            float xj[CC][3], sqj[CC];
            #pragma unroll
            for (int d = 0; d < CC; ++d) {
                xj[d][0] = sX[j * 19 + d * 3 + 0];
                xj[d][1] = sX[j * 19 + d * 3 + 1];
                xj[d][2] = sX[j * 19 + d * 3 + 2];
                sqj[d] = xj[d][0] * xj[d][0] + xj[d][1] * xj[d][1] + xj[d][2] * xj[d][2];
            }
            const bool full = fulli || ((padj & 0x80) != 0);
            float mn = 3.0e38f;
            if (full) {
                // class2: min over ALL channel pairs
                #pragma unroll
                for (int c = 0; c < CC; ++c) {
                    #pragma unroll
                    for (int d = 0; d < CC; ++d) {
                        float dot = fmaf(xi[c][0], xj[d][0],
                                    fmaf(xi[c][1], xj[d][1], xi[c][2] * xj[d][2]));
                        float d2 = fmaf(-2.0f, dot, sqi[c] + sqj[d]);
                        d2 = d2 > 0.0f ? d2 : 0.0f;
                        mn = fminf(mn, d2);
                    }
                }
            } else {
                // class0: min over unpadded pairs only
                #pragma unroll
                for (int c = 0; c < CC; ++c) {
                    if ((padi >> c) & 1) continue;        // warp-uniform skip
                    #pragma unroll
                    for (int d = 0; d < CC; ++d) {
                        float dot = fmaf(xi[c][0], xj[d][0],
                                    fmaf(xi[c][1], xj[d][1], xi[c][2] * xj[d][2]));
                        float d2 = fmaf(-2.0f, dot, sqi[c] + sqj[d]);
                        d2 = d2 > 0.0f ? d2 : 0.0f;
                        bool ok = !((padj >> d) & 1);
                        mn = ok ? fminf(mn, d2) : mn;
                    }
                }
            }
            unsigned cls = full ? 2u : 0u;
            key = ((unsigned long long)cls << 41)
                | ((unsigned long long)__float_as_uint(mn) << 9)
                | (unsigned)j;
        }
        // sorted-insert into register top-9 (ascending)
        if (key < best[KK - 1]) {
            best[KK - 1] = key;
            #pragma unroll
            for (int t = KK - 1; t > 0; --t) {
                if (best[t] < best[t - 1]) {
                    unsigned long long tmp = best[t];
                    best[t] = best[t - 1];
                    best[t - 1] = tmp;
                }
            }
        }
    }

    // warp merge of 32 sorted lists; keys are unique (index embedded)
    int p = 0;
    const int seci = sSec[il];
    for (int r = 0; r < KK; ++r) {
        unsigned long long v = (p < KK) ? best[p] : ~0ull;
        unsigned long long m = v;
        #pragma unroll
        for (int off = 16; off; off >>= 1) {
            unsigned long long o = __shfl_xor_sync(0xffffffffu, m, off);
            m = (o < m) ? o : m;
        }
        if (v == m) {       // exactly one winner lane
            ++p;
            int j = (int)(m & 511u);
            unsigned cls = (unsigned)(m >> 41);
            float d2 = __uint_as_float((unsigned)((m >> 9) & 0xffffffffu));
            float dk;
            if (cls == 0u)      dk = sqrtf(d2);
            else if (cls == 1u) dk = BIGF;
            else                dk = BIGF + sqrtf(d2);
            bool valid = (cls == 0u) && (seci == sSec[j]);
            int dstg = valid ? (gbase + j) : -1;
            size_t o0 = (size_t)ig * KK + r;
            out[o0]                      = dk;
            out[(size_t)NTOT * KK + o0]  = (float)ig;
            out[2 * (size_t)NTOT * KK + o0] = (float)dstg;
            out[3 * (size_t)NTOT * KK + o0] = valid ? 1.0f : 0.0f;
        }
    }
}

__global__ void edges_kernel(float* __restrict__ out)
{
    const int GLB_PER = 2 * LL - 1;   // 1023
    const int SEQ_PER = 2 * (LL - 2); // 1020
    const int NG = BB * GLB_PER;      // 8184
    const int NS = BB * SEQ_PER;      // 8160
    float* g = out + 4 * (size_t)NTOT * KK;   // 147456
    float* s = g + 2 * NG;                    // 163824

    int t = blockIdx.x * blockDim.x + threadIdx.x;
    if (t < NG) {
        int b = t / GLB_PER, e = t % GLB_PER;
        int srcl = (e < LL) ? 0 : (e - LL + 1);
        int dstl = (e < LL) ? e : 0;
        g[t]      = (float)(srcl + b * LL);
        g[NG + t] = (float)(dstl + b * LL);
    } else if (t < NG + NS) {
        int u = t - NG;
        int b = u / SEQ_PER, e = u % SEQ_PER;
        int half = LL - 2; // 510
        int srcl, dstl;
        if (e < half) { srcl = 1 + e;          dstl = 2 + e; }
        else          { srcl = 2 + (e - half); dstl = 1 + (e - half); }
        s[u]      = (float)(srcl + b * LL);
        s[NS + u] = (float)(dstl + b * LL);
    }
}

extern "C" void kernel_launch(void* const* d_in, const int* in_sizes, int n_in,
                              void* d_out, int out_size)
{
    const float* X   = (const float*)d_in[0];
    const int*   AP  = (const int*)d_in[1];
    const int*   S   = (const int*)d_in[2];
    const int*   sec = (const int*)d_in[3];
    float* out = (float*)d_out;

    dim3 grid(BB * (LL / ROWS_PER_BLOCK));   // 512 CTAs
    knn_kernel<<<grid, THREADS>>>(X, AP, S, sec, out);

    const int nEdgeThreads = BB * (2 * LL - 1) + BB * 2 * (LL - 2);  // 16344? -> 8184+8160=16344
    edges_kernel<<<(nEdgeThreads + 255) / 256, 256>>>(out);
}

// round 5
// speedup vs baseline: 2.8632x; 2.8632x over previous
#include <cuda_runtime.h>
#include <cstdint>

#define BB 8
#define LL 512
#define CC 6
#define KK 9
#define NTOT (BB*LL)
#define BIGF 1e10f
#define POISON 5e29f
#define REAL_THR 1e9f            // on sqrt scale: real dists < ~200, poisoned >= 7e14

#define THREADS 512
#define CTAS_PER_GRAPH 16
#define NODE_STRIDE 28            // floats per node in smem (7 quads -> conflict-free)
#define SMEM_BYTES (LL * NODE_STRIDE * 4)

// Output layout (float32, reference return order):
//   [0)       dknn  : 36864
//   [36864)   src   : 36864
//   [73728)   dst   : 36864
//   [110592)  valid : 36864
//   [147456)  glb   : 16368
//   [163824)  seq   : 16320   -> total 180144

extern "C" __global__ void __launch_bounds__(THREADS, 1)
knn_kernel(const float* __restrict__ X, const int* __restrict__ AP,
           const int* __restrict__ S, const int* __restrict__ sec,
           float* __restrict__ out)
{
    extern __shared__ float sX[];        // 512 nodes * 28 floats

    const int g     = blockIdx.x / CTAS_PER_GRAPH;
    const int part  = blockIdx.x % CTAS_PER_GRAPH;
    const int gbase = g * LL;
    const int tid   = threadIdx.x;

    // ---- structural edges (independent of smem; folded into this kernel) ----
    {
        const int GLB_PER = 2*LL - 1, SEQ_PER = 2*(LL - 2);
        const int NG = BB*GLB_PER, NS = BB*SEQ_PER;
        float* gq = out + 4*(size_t)NTOT*KK;
        float* sq = gq + 2*NG;
        int t = blockIdx.x * THREADS + tid;
        if (t < NG) {
            int b = t / GLB_PER, e = t % GLB_PER;
            int srcl = (e < LL) ? 0 : (e - LL + 1);
            int dstl = (e < LL) ? e : 0;
            gq[t]      = (float)(srcl + b*LL);
            gq[NG + t] = (float)(dstl + b*LL);
        } else if (t < NG + NS) {
            int u = t - NG;
            int b = u / SEQ_PER, e = u % SEQ_PER;
            int half = LL - 2;
            int srcl = (e < half) ? (1 + e) : (2 + (e - half));
            int dstl = (e < half) ? (2 + e) : (1 + (e - half));
            sq[u]      = (float)(srcl + b*LL);
            sq[NS + u] = (float)(dstl + b*LL);
        }
    }

    // ---- stage graph table: node j -> 6 x float4(x, y, z, sq or POISON) ----
    {
        int j = tid;                                  // 512 nodes, 512 threads
        const float* xp  = X  + (size_t)(gbase + j) * (CC*3);
        const int*   app = AP + (size_t)(gbase + j) * CC;
        bool bos = (S[gbase + j] == 0);
        #pragma unroll
        for (int c = 0; c < CC; ++c) {
            float x = xp[c*3+0], y = xp[c*3+1], z = xp[c*3+2];
            float sq = x*x + y*y + z*z;               // same expression as verified round-1
            if (bos || app[c] == 0) sq = POISON;      // padded channel / BOS node -> never wins
            *(float4*)(sX + (size_t)j*NODE_STRIDE + c*4) = make_float4(x, y, z, sq);
        }
    }
    __syncthreads();

    const int warp = tid >> 5, lane = tid & 31;
    const int slot = part * 16 + warp;                // 0..255, 2 rows each

    #pragma unroll 1
    for (int rr = 0; rr < 2; ++rr) {
        const int il = slot * 2 + rr;                 // local row
        const int ig = gbase + il;

        // row-constant data (poisoned sq covers padded-c and BOS-row cases)
        float xi0[CC], xi1[CC], xi2[CC], sqi[CC];
        #pragma unroll
        for (int c = 0; c < CC; ++c) {
            float4 v = *(const float4*)(sX + (size_t)il*NODE_STRIDE + c*4);
            xi0[c] = v.x; xi1[c] = v.y; xi2[c] = v.z; sqi[c] = v.w;
        }

        unsigned bk[KK]; int bj[KK];                  // sorted ascending (stable)
        #pragma unroll
        for (int t = 0; t < KK; ++t) { bk[t] = 0xFFFFFFFFu; bj[t] = 511; }

        #pragma unroll 2
        for (int jt = 0; jt < LL/32; ++jt) {
            const int j = (jt << 5) | lane;
            const float4* nd = (const float4*)(sX + (size_t)j*NODE_STRIDE);
            float4 q0 = nd[0], q1 = nd[1], q2 = nd[2], q3 = nd[3], q4 = nd[4], q5 = nd[5];

            float m = 3.4e38f;
            #pragma unroll
            for (int c = 0; c < CC; ++c) {
                // round-1-exact arithmetic: dot fma-chain, s = sqi+sqj, d2 = fma(-2,dot,s)
                float d0 = fmaf(xi0[c], q0.x, fmaf(xi1[c], q0.y, xi2[c]*q0.z));
                float d1 = fmaf(xi0[c], q1.x, fmaf(xi1[c], q1.y, xi2[c]*q1.z));
                float d2_ = fmaf(xi0[c], q2.x, fmaf(xi1[c], q2.y, xi2[c]*q2.z));
                float d3 = fmaf(xi0[c], q3.x, fmaf(xi1[c], q3.y, xi2[c]*q3.z));
                float d4 = fmaf(xi0[c], q4.x, fmaf(xi1[c], q4.y, xi2[c]*q4.z));
                float d5 = fmaf(xi0[c], q5.x, fmaf(xi1[c], q5.y, xi2[c]*q5.z));
                float e0 = fmaf(-2.0f, d0,  sqi[c] + q0.w);
                float e1 = fmaf(-2.0f, d1,  sqi[c] + q1.w);
                float e2 = fmaf(-2.0f, d2_, sqi[c] + q2.w);
                float e3 = fmaf(-2.0f, d3,  sqi[c] + q3.w);
                float e4 = fmaf(-2.0f, d4,  sqi[c] + q4.w);
                float e5 = fmaf(-2.0f, d5,  sqi[c] + q5.w);
                float acc = fminf(fminf(fminf(e0, e1), fminf(e2, e3)), fminf(e4, e5));
                m = fminf(m, acc);
            }
            m = fmaxf(m, 0.0f);                       // == reference's per-pair clamp
            // rank on the sqrt'd distance: matches reference top_k key bit-for-bit
            // (min of rounded sqrts == rounded sqrt of min, by monotonicity)
            unsigned kk = __float_as_uint(sqrtf(m));
            int      kj = j;

            // branchless stable insertion into sorted top-9 (no-op if kk too large)
            #pragma unroll
            for (int t = KK - 1; t >= 1; --t) {
                bool geq = (kk >= bk[t-1]);
                unsigned hi = geq ? kk : bk[t-1];
                int     hij = geq ? kj : bj[t-1];
                bool lt = (hi < bk[t]);
                bk[t] = lt ? hi  : bk[t];
                bj[t] = lt ? hij : bj[t];
            }
            bool lt0 = (kk < bk[0]);
            bk[0] = lt0 ? kk : bk[0];
            bj[0] = lt0 ? kj : bj[0];
        }

        // ---- warp merge: 9 rounds of warp-min over each lane's head ----
        const int seci = sec[ig];
        #pragma unroll 1
        for (int r = 0; r < KK; ++r) {
            unsigned long long c = (((unsigned long long)bk[0]) << 9) | (unsigned)bj[0];
            unsigned long long mn = c;
            #pragma unroll
            for (int off = 16; off; off >>= 1) {
                unsigned long long o = __shfl_xor_sync(0xffffffffu, mn, off);
                mn = (o < mn) ? o : mn;
            }
            if (c == mn) {                            // unique winner ((key,j) distinct)
                int j = (int)(mn & 511u);
                float dv = __uint_as_float(bk[0]);    // sqrt'd distance
                bool real = (dv < REAL_THR);
                bool valid = real && (seci == sec[gbase + j]);
                size_t o0 = (size_t)ig * KK + r;
                out[o0]                        = real ? dv : BIGF;
                out[(size_t)NTOT*KK     + o0]  = (float)ig;
                out[2*(size_t)NTOT*KK   + o0]  = valid ? (float)(gbase + j) : -1.0f;
                out[3*(size_t)NTOT*KK   + o0]  = valid ? 1.0f : 0.0f;
                #pragma unroll
                for (int t = 0; t < KK-1; ++t) { bk[t] = bk[t+1]; bj[t] = bj[t+1]; }
                bk[KK-1] = 0xFFFFFFFFu; bj[KK-1] = 511;
            }
        }
    }
}

extern "C" void kernel_launch(void* const* d_in, const int* in_sizes, int n_in,
                              void* d_out, int out_size)
{
    const float* X   = (const float*)d_in[0];
    const int*   AP  = (const int*)d_in[1];
    const int*   S   = (const int*)d_in[2];
    const int*   sec = (const int*)d_in[3];
    float* out = (float*)d_out;

    cudaFuncSetAttribute((const void*)knn_kernel,
                         cudaFuncAttributeMaxDynamicSharedMemorySize, SMEM_BYTES);
    knn_kernel<<<BB * CTAS_PER_GRAPH, THREADS, SMEM_BYTES>>>(X, AP, S, sec, out);
}

// round 7
// speedup vs baseline: 3.4660x; 1.2105x over previous
#include <cuda_runtime.h>
#include <cstdint>

#define BB 8
#define LL 512
#define CC 6
#define KK 9
#define NTOT (BB*LL)
#define BIGF 1e10f
#define POISON 5e29f
#define REAL_THR 1e9f            // on sqrt scale: real dists < ~200, poisoned >= ~7e14

#define THREADS 512
#define CTAS_PER_GRAPH 16
#define NODE_STRIDE 28            // floats per node in smem (112B -> conflict-free LDS.128)
#define SMEM_BYTES (LL * NODE_STRIDE * 4)

// node layout (floats): [x01 x01' y01 y01' | z01 z01' sq01 sq01'] for channel-pair (0,1),
// then pairs (2,3), (4,5).  As ulonglong2: nd[2*dp] = {xpair, ypair}, nd[2*dp+1] = {zpair, sqpair}.

#define F32X2_MUL(o,a,b)   asm("mul.rn.f32x2 %0, %1, %2;"     : "=l"(o) : "l"(a), "l"(b))
#define F32X2_ADD(o,a,b)   asm("add.rn.f32x2 %0, %1, %2;"     : "=l"(o) : "l"(a), "l"(b))
#define F32X2_FMA(o,a,b,c) asm("fma.rn.f32x2 %0, %1, %2, %3;" : "=l"(o) : "l"(a), "l"(b), "l"(c))
#define PACK2(o,f)         asm("mov.b64 %0, {%1, %1};"        : "=l"(o) : "r"(__float_as_uint(f)))
#define UNPACK2(lo,hi,v)   asm("mov.b64 {%0, %1}, %2;"        : "=r"(lo), "=r"(hi) : "l"(v))

// Output layout (float32, reference return order):
//   [0) dknn 36864 | [36864) src | [73728) dst | [110592) valid | [147456) glb 16368 | [163824) seq 16320

extern "C" __global__ void __launch_bounds__(THREADS, 1)
knn_kernel(const float* __restrict__ X, const int* __restrict__ AP,
           const int* __restrict__ S, const int* __restrict__ sec,
           float* __restrict__ out)
{
    extern __shared__ float sX[];        // 512 nodes * 28 floats

    const int g     = blockIdx.x / CTAS_PER_GRAPH;
    const int part  = blockIdx.x % CTAS_PER_GRAPH;
    const int gbase = g * LL;
    const int tid   = threadIdx.x;

    // ---- structural edges (independent of smem; folded in) ----
    {
        const int GLB_PER = 2*LL - 1, SEQ_PER = 2*(LL - 2);
        const int NG = BB*GLB_PER, NS = BB*SEQ_PER;
        float* gq = out + 4*(size_t)NTOT*KK;
        float* sq = gq + 2*NG;
        int t = blockIdx.x * THREADS + tid;
        if (t < NG) {
            int b = t / GLB_PER, e = t % GLB_PER;
            int srcl = (e < LL) ? 0 : (e - LL + 1);
            int dstl = (e < LL) ? e : 0;
            gq[t]      = (float)(srcl + b*LL);
            gq[NG + t] = (float)(dstl + b*LL);
        } else if (t < NG + NS) {
            int u = t - NG;
            int b = u / SEQ_PER, e = u % SEQ_PER;
            int half = LL - 2;
            int srcl = (e < half) ? (1 + e) : (2 + (e - half));
            int dstl = (e < half) ? (2 + e) : (1 + (e - half));
            sq[u]      = (float)(srcl + b*LL);
            sq[NS + u] = (float)(dstl + b*LL);
        }
    }

    // ---- stage graph table, channel-paired for f32x2 ----
    {
        int j = tid;                                  // 512 nodes, 512 threads
        const float* xp  = X  + (size_t)(gbase + j) * (CC*3);
        const int*   app = AP + (size_t)(gbase + j) * CC;
        bool bos = (S[gbase + j] == 0);
        float xs[CC], ys[CC], zs[CC], ws[CC];
        #pragma unroll
        for (int c = 0; c < CC; ++c) {
            float x = xp[c*3+0], y = xp[c*3+1], z = xp[c*3+2];
            float sq = x*x + y*y + z*z;               // identical expression to passing kernel
            if (bos || app[c] == 0) sq = POISON;
            xs[c] = x; ys[c] = y; zs[c] = z; ws[c] = sq;
        }
        float* base = sX + (size_t)j * NODE_STRIDE;
        #pragma unroll
        for (int dp = 0; dp < 3; ++dp) {
            int c0 = 2*dp, c1 = 2*dp + 1;
            *(float4*)(base + dp*8 + 0) = make_float4(xs[c0], xs[c1], ys[c0], ys[c1]);
            *(float4*)(base + dp*8 + 4) = make_float4(zs[c0], zs[c1], ws[c0], ws[c1]);
        }
    }
    __syncthreads();

    const int warp = tid >> 5, lane = tid & 31;
    const int slot = part * 16 + warp;                // 0..255, 2 rows each

    unsigned long long neg2; PACK2(neg2, -2.0f);

    #pragma unroll 1
    for (int rr = 0; rr < 2; ++rr) {
        const int il = slot * 2 + rr;                 // local row
        const int ig = gbase + il;

        // row-constant broadcast pairs (one per row channel c)
        unsigned long long bx0[CC], bx1[CC], bx2[CC], bsq[CC];
        {
            const float* base = sX + (size_t)il * NODE_STRIDE;
            #pragma unroll
            for (int dp = 0; dp < 3; ++dp) {
                float4 a = *(const float4*)(base + dp*8 + 0);  // xc0 xc1 yc0 yc1
                float4 b = *(const float4*)(base + dp*8 + 4);  // zc0 zc1 wc0 wc1
                int c0 = 2*dp, c1 = 2*dp + 1;
                PACK2(bx0[c0], a.x); PACK2(bx0[c1], a.y);
                PACK2(bx1[c0], a.z); PACK2(bx1[c1], a.w);
                PACK2(bx2[c0], b.x); PACK2(bx2[c1], b.y);
                PACK2(bsq[c0], b.z); PACK2(bsq[c1], b.w);
            }
        }

        unsigned bk[KK]; int bj[KK];                  // sorted ascending (stable)
        #pragma unroll
        for (int t = 0; t < KK; ++t) { bk[t] = 0xFFFFFFFFu; bj[t] = 511; }

        #pragma unroll 2
        for (int jt = 0; jt < LL/32; ++jt) {
            const int j = (jt << 5) | lane;
            const ulonglong2* nd = (const ulonglong2*)(sX + (size_t)j*NODE_STRIDE);
            ulonglong2 p0 = nd[0], p1 = nd[1], p2 = nd[2],
                       p3 = nd[3], p4 = nd[4], p5 = nd[5];

            float m = 3.4e38f;
            #pragma unroll
            for (int c = 0; c < CC; ++c) {
                unsigned long long t0, t1, t2, s0, s1, s2, e0, e1, e2;
                // dot chain per half: fma(x, qx, fma(y, qy, z*qz)) — identical to scalar version
                F32X2_MUL(t0, bx2[c], p1.x); F32X2_FMA(t0, bx1[c], p0.y, t0); F32X2_FMA(t0, bx0[c], p0.x, t0);
                F32X2_MUL(t1, bx2[c], p3.x); F32X2_FMA(t1, bx1[c], p2.y, t1); F32X2_FMA(t1, bx0[c], p2.x, t1);
                F32X2_MUL(t2, bx2[c], p5.x); F32X2_FMA(t2, bx1[c], p4.y, t2); F32X2_FMA(t2, bx0[c], p4.x, t2);
                // s = sqi + sqj ; e = fma(-2, dot, s) — identical rounding to scalar version
                F32X2_ADD(s0, bsq[c], p1.y); F32X2_FMA(e0, neg2, t0, s0);
                F32X2_ADD(s1, bsq[c], p3.y); F32X2_FMA(e1, neg2, t1, s1);
                F32X2_ADD(s2, bsq[c], p5.y); F32X2_FMA(e2, neg2, t2, s2);
                unsigned l0, h0, l1, h1, l2, h2;
                UNPACK2(l0, h0, e0); UNPACK2(l1, h1, e1); UNPACK2(l2, h2, e2);
                float m01 = fminf(__uint_as_float(l0), __uint_as_float(h0));
                float m23 = fminf(__uint_as_float(l1), __uint_as_float(h1));
                float m45 = fminf(__uint_as_float(l2), __uint_as_float(h2));
                float acc = fminf(fminf(m01, m23), m45);
                m = fminf(m, acc);
            }
            m = fmaxf(m, 0.0f);                       // == reference's per-pair clamp
            unsigned kk = __float_as_uint(sqrtf(m));  // rank on sqrt'd distance (as reference)
            int      kj = j;

            // branchless stable insertion into sorted top-9 (no-op if kk too large)
            #pragma unroll
            for (int t = KK - 1; t >= 1; --t) {
                bool geq = (kk >= bk[t-1]);
                unsigned hi = geq ? kk : bk[t-1];
                int     hij = geq ? kj : bj[t-1];
                bool lt = (hi < bk[t]);
                bk[t] = lt ? hi  : bk[t];
                bj[t] = lt ? hij : bj[t];
            }
            bool lt0 = (kk < bk[0]);
            bk[0] = lt0 ? kk : bk[0];
            bj[0] = lt0 ? kj : bj[0];
        }

        // ---- warp merge: 9 rounds of warp-min over each lane's head ----
        const int seci = sec[ig];
        #pragma unroll 1
        for (int r = 0; r < KK; ++r) {
            unsigned long long c = (((unsigned long long)bk[0]) << 9) | (unsigned)bj[0];
            unsigned long long mn = c;
            #pragma unroll
            for (int off = 16; off; off >>= 1) {
                unsigned long long o = __shfl_xor_sync(0xffffffffu, mn, off);
                mn = (o < mn) ? o : mn;
            }
            if (c == mn) {                            // unique winner ((key,j) distinct)
                int j = (int)(mn & 511u);
                float dv = __uint_as_float(bk[0]);    // sqrt'd distance
                bool real = (dv < REAL_THR);
                bool valid = real && (seci == sec[gbase + j]);
                size_t o0 = (size_t)ig * KK + r;
                out[o0]                        = real ? dv : BIGF;
                out[(size_t)NTOT*KK     + o0]  = (float)ig;
                out[2*(size_t)NTOT*KK   + o0]  = valid ? (float)(gbase + j) : -1.0f;
                out[3*(size_t)NTOT*KK   + o0]  = valid ? 1.0f : 0.0f;
                #pragma unroll
                for (int t = 0; t < KK-1; ++t) { bk[t] = bk[t+1]; bj[t] = bj[t+1]; }
                bk[KK-1] = 0xFFFFFFFFu; bj[KK-1] = 511;
            }
        }
    }
}

extern "C" void kernel_launch(void* const* d_in, const int* in_sizes, int n_in,
                              void* d_out, int out_size)
{
    const float* X   = (const float*)d_in[0];
    const int*   AP  = (const int*)d_in[1];
    const int*   S   = (const int*)d_in[2];
    const int*   sec = (const int*)d_in[3];
    float* out = (float*)d_out;

    cudaFuncSetAttribute((const void*)knn_kernel,
                         cudaFuncAttributeMaxDynamicSharedMemorySize, SMEM_BYTES);
    knn_kernel<<<BB * CTAS_PER_GRAPH, THREADS, SMEM_BYTES>>>(X, AP, S, sec, out);
}

// round 9
// speedup vs baseline: 3.5122x; 1.0133x over previous
#include <cuda_runtime.h>
#include <cstdint>

#define BB 8
#define LL 512
#define CC 6
#define KK 9
#define NTOT (BB*LL)
#define BIGF 1e10f
#define POISON 5e29f
#define REAL_THR_D2 1e20f         // real d2 <= ~3e4, poisoned >= ~4e29

#define THREADS 512
#define CTAS_PER_GRAPH 16
#define NODE_STRIDE 28            // floats per node (112B -> conflict-free LDS.128)
#define SCR_STRIDE 17             // u32 scratch stride per thread (odd -> conflict-free)

// dynamic smem: table 512*28 f32 | scratch 512*17 u32 | sec 512 i32
#define SMEM_FLOATS (LL*NODE_STRIDE + LL*SCR_STRIDE + LL)
#define SMEM_BYTES  (SMEM_FLOATS * 4)

#define F32X2_MUL(o,a,b)   asm("mul.rn.f32x2 %0, %1, %2;"     : "=l"(o) : "l"(a), "l"(b))
#define F32X2_ADD(o,a,b)   asm("add.rn.f32x2 %0, %1, %2;"     : "=l"(o) : "l"(a), "l"(b))
#define F32X2_FMA(o,a,b,c) asm("fma.rn.f32x2 %0, %1, %2, %3;" : "=l"(o) : "l"(a), "l"(b), "l"(c))
#define PACK2(o,f)         asm("mov.b64 %0, {%1, %1};"        : "=l"(o) : "r"(__float_as_uint(f)))
#define UNPACK2(lo,hi,v)   asm("mov.b64 {%0, %1}, %2;"        : "=r"(lo), "=r"(hi) : "l"(v))

// compare-exchange on packed (d2bits<<9 | idx) u64s — lexicographic (key, idx)
#define CE(a,b) { unsigned long long _x=v[a], _y=v[b]; bool _p=_x<_y; v[a]=_p?_x:_y; v[b]=_p?_y:_x; }

// Output layout (float32, reference return order):
//   [0) dknn 36864 | [36864) src | [73728) dst | [110592) valid | [147456) glb 16368 | [163824) seq 16320

extern "C" __global__ void __launch_bounds__(THREADS, 1)
knn_kernel(const float* __restrict__ X, const int* __restrict__ AP,
           const int* __restrict__ S, const int* __restrict__ sec,
           float* __restrict__ out)
{
    extern __shared__ float sX[];
    unsigned* sScr = (unsigned*)(sX + LL*NODE_STRIDE);
    int*      sSec = (int*)(sScr + LL*SCR_STRIDE);

    const int g     = blockIdx.x / CTAS_PER_GRAPH;
    const int part  = blockIdx.x % CTAS_PER_GRAPH;
    const int gbase = g * LL;
    const int tid   = threadIdx.x;

    // ---- structural edges (independent of smem; folded in) ----
    {
        const int GLB_PER = 2*LL - 1, SEQ_PER = 2*(LL - 2);
        const int NG = BB*GLB_PER, NS = BB*SEQ_PER;
        float* gq = out + 4*(size_t)NTOT*KK;
        float* sq = gq + 2*NG;
        int t = blockIdx.x * THREADS + tid;
        if (t < NG) {
            int b = t / GLB_PER, e = t % GLB_PER;
            int srcl = (e < LL) ? 0 : (e - LL + 1);
            int dstl = (e < LL) ? e : 0;
            gq[t]      = (float)(srcl + b*LL);
            gq[NG + t] = (float)(dstl + b*LL);
        } else if (t < NG + NS) {
            int u = t - NG;
            int b = u / SEQ_PER, e = u % SEQ_PER;
            int half = LL - 2;
            int srcl = (e < half) ? (1 + e) : (2 + (e - half));
            int dstl = (e < half) ? (2 + e) : (1 + (e - half));
            sq[u]      = (float)(srcl + b*LL);
            sq[NS + u] = (float)(dstl + b*LL);
        }
    }

    // ---- stage graph table, channel-paired for f32x2 (identical to passing kernel) ----
    {
        int j = tid;
        const float* xp  = X  + (size_t)(gbase + j) * (CC*3);
        const int*   app = AP + (size_t)(gbase + j) * CC;
        bool bos = (S[gbase + j] == 0);
        float xs[CC], ys[CC], zs[CC], ws[CC];
        #pragma unroll
        for (int c = 0; c < CC; ++c) {
            float x = xp[c*3+0], y = xp[c*3+1], z = xp[c*3+2];
            float sq = x*x + y*y + z*z;
            if (bos || app[c] == 0) sq = POISON;
            xs[c] = x; ys[c] = y; zs[c] = z; ws[c] = sq;
        }
        float* base = sX + (size_t)j * NODE_STRIDE;
        #pragma unroll
        for (int dp = 0; dp < 3; ++dp) {
            int c0 = 2*dp, c1 = 2*dp + 1;
            *(float4*)(base + dp*8 + 0) = make_float4(xs[c0], xs[c1], ys[c0], ys[c1]);
            *(float4*)(base + dp*8 + 4) = make_float4(zs[c0], zs[c1], ws[c0], ws[c1]);
        }
        sSec[j] = sec[gbase + j];
    }
    __syncthreads();

    const int warp = tid >> 5, lane = tid & 31;
    const int slot = part * 16 + warp;                // 0..255, 2 rows each

    unsigned long long neg2; PACK2(neg2, -2.0f);

    #pragma unroll 1
    for (int rr = 0; rr < 2; ++rr) {
        const int il = slot * 2 + rr;
        const int ig = gbase + il;

        // row-constant broadcast pairs
        unsigned long long bx0[CC], bx1[CC], bx2[CC], bsq[CC];
        {
            const float* base = sX + (size_t)il * NODE_STRIDE;
            #pragma unroll
            for (int dp = 0; dp < 3; ++dp) {
                float4 a = *(const float4*)(base + dp*8 + 0);
                float4 b = *(const float4*)(base + dp*8 + 4);
                int c0 = 2*dp, c1 = 2*dp + 1;
                PACK2(bx0[c0], a.x); PACK2(bx0[c1], a.y);
                PACK2(bx1[c0], a.z); PACK2(bx1[c1], a.w);
                PACK2(bx2[c0], b.x); PACK2(bx2[c1], b.y);
                PACK2(bsq[c0], b.z); PACK2(bsq[c1], b.w);
            }
        }

        // ---- fully independent distance loop: 1 STS per candidate, no selection here ----
        #pragma unroll 2
        for (int jt = 0; jt < LL/32; ++jt) {
            const int j = (jt << 5) | lane;
            const ulonglong2* nd = (const ulonglong2*)(sX + (size_t)j*NODE_STRIDE);
            ulonglong2 p0 = nd[0], p1 = nd[1], p2 = nd[2],
                       p3 = nd[3], p4 = nd[4], p5 = nd[5];

            float m = 3.4e38f;
            #pragma unroll
            for (int c = 0; c < CC; ++c) {
                unsigned long long t0, t1, t2, s0, s1, s2, e0, e1, e2;
                F32X2_MUL(t0, bx2[c], p1.x); F32X2_FMA(t0, bx1[c], p0.y, t0); F32X2_FMA(t0, bx0[c], p0.x, t0);
                F32X2_MUL(t1, bx2[c], p3.x); F32X2_FMA(t1, bx1[c], p2.y, t1); F32X2_FMA(t1, bx0[c], p2.x, t1);
                F32X2_MUL(t2, bx2[c], p5.x); F32X2_FMA(t2, bx1[c], p4.y, t2); F32X2_FMA(t2, bx0[c], p4.x, t2);
                F32X2_ADD(s0, bsq[c], p1.y); F32X2_FMA(e0, neg2, t0, s0);
                F32X2_ADD(s1, bsq[c], p3.y); F32X2_FMA(e1, neg2, t1, s1);
                F32X2_ADD(s2, bsq[c], p5.y); F32X2_FMA(e2, neg2, t2, s2);
                unsigned l0, h0, l1, h1, l2, h2;
                UNPACK2(l0, h0, e0); UNPACK2(l1, h1, e1); UNPACK2(l2, h2, e2);
                float m01 = fminf(__uint_as_float(l0), __uint_as_float(h0));
                float m23 = fminf(__uint_as_float(l1), __uint_as_float(h1));
                float m45 = fminf(__uint_as_float(l2), __uint_as_float(h2));
                float acc = fminf(fminf(m01, m23), m45);
                m = fminf(m, acc);
            }
            m = fmaxf(m, 0.0f);                       // reference's per-pair clamp
            sScr[tid * SCR_STRIDE + jt] = __float_as_uint(m);   // nonneg float: uint-order == float-order
        }

        // ---- per-lane selection: load 16 keys, pack (key<<9|j), Batcher sort-16 ----
        unsigned long long v[16];
        #pragma unroll
        for (int t = 0; t < 16; ++t) {
            unsigned kk = sScr[tid * SCR_STRIDE + t];
            v[t] = (((unsigned long long)kk) << 9) | (unsigned)((t << 5) | lane);
        }
        // Batcher odd-even mergesort, 16 inputs, 63 CEs
        CE(0,1) CE(2,3) CE(4,5) CE(6,7) CE(8,9) CE(10,11) CE(12,13) CE(14,15)
        CE(0,2) CE(1,3) CE(4,6) CE(5,7) CE(8,10) CE(9,11) CE(12,14) CE(13,15)
        CE(1,2) CE(5,6) CE(9,10) CE(13,14)
        CE(0,4) CE(1,5) CE(2,6) CE(3,7) CE(8,12) CE(9,13) CE(10,14) CE(11,15)
        CE(2,4) CE(3,5) CE(10,12) CE(11,13)
        CE(1,2) CE(3,4) CE(5,6) CE(9,10) CE(11,12) CE(13,14)
        CE(0,8) CE(1,9) CE(2,10) CE(3,11) CE(4,12) CE(5,13) CE(6,14) CE(7,15)
        CE(4,8) CE(5,9) CE(6,10) CE(7,11)
        CE(2,4) CE(3,5) CE(6,8) CE(7,9) CE(10,12) CE(11,13)
        CE(1,2) CE(3,4) CE(5,6) CE(7,8) CE(9,10) CE(11,12) CE(13,14)

        // ---- warp merge via redux: 9 rounds, lexicographic (key, idx) min ----
        const int seci = sSec[il];
        #pragma unroll 1
        for (int r = 0; r < KK; ++r) {
            unsigned mykey = (unsigned)(v[0] >> 9);
            unsigned kmin  = __reduce_min_sync(0xffffffffu, mykey);
            unsigned myidx = (unsigned)v[0] & 511u;
            unsigned cand  = (mykey == kmin) ? myidx : 1023u;
            unsigned imin  = __reduce_min_sync(0xffffffffu, cand);
            if (mykey == kmin && myidx == imin) {     // exactly one winner
                float d2v  = __uint_as_float(kmin);
                bool  real = (d2v < REAL_THR_D2);
                float dv   = real ? sqrtf(d2v) : BIGF;
                bool  valid = real && (seci == sSec[imin]);
                size_t o0 = (size_t)ig * KK + r;
                out[o0]                        = dv;
                out[(size_t)NTOT*KK     + o0]  = (float)ig;
                out[2*(size_t)NTOT*KK   + o0]  = valid ? (float)(gbase + (int)imin) : -1.0f;
                out[3*(size_t)NTOT*KK   + o0]  = valid ? 1.0f : 0.0f;
                #pragma unroll
                for (int t = 0; t < 8; ++t) v[t] = v[t+1];   // pop head (winner only)
            }
        }
    }
}

extern "C" void kernel_launch(void* const* d_in, const int* in_sizes, int n_in,
                              void* d_out, int out_size)
{
    const float* X   = (const float*)d_in[0];
    const int*   AP  = (const int*)d_in[1];
    const int*   S   = (const int*)d_in[2];
    const int*   sec = (const int*)d_in[3];
    float* out = (float*)d_out;

    cudaFuncSetAttribute((const void*)knn_kernel,
                         cudaFuncAttributeMaxDynamicSharedMemorySize, SMEM_BYTES);
    knn_kernel<<<BB * CTAS_PER_GRAPH, THREADS, SMEM_BYTES>>>(X, AP, S, sec, out);
}